// round 1
// baseline (speedup 1.0000x reference)
#include <cuda_runtime.h>
#include <cuda_bf16.h>

// BatchDepthwiseCrossCorrelation:
//   x:         [8, 256, 64, 64]  f32   (d_in[0], 8388608 elems)
//   templates: [8, 8, 256, 7, 7] f32   (d_in[1], 802816 elems)
//   out:       [8, 8, 256, 64, 64] f32 (67108864 elems)
// out[nt,b,ch,y,x] = sum_{ky,kx} x[b,ch,y+ky-3,x+kx-3] * t[nt,b,ch,ky,kx]  (zero pad)

#define BSNC   2048            // bs*nc fused channel count
#define HI     64
#define WI     64
#define PLANE  (HI*WI)
#define KH     7
#define KW     7
#define TAPS   49
#define PAD    3
#define NT     8
#define RPB    32              // output rows per block
#define SROWS  (RPB + KH - 1)  // 38
#define SP     72              // smem row pitch in words (16B-aligned rows)
#define NTHREADS 256

__device__ __forceinline__ unsigned long long ffma2(unsigned long long a,
                                                    unsigned long long b,
                                                    unsigned long long c) {
    unsigned long long d;
    asm("fma.rn.f32x2 %0, %1, %2, %3;" : "=l"(d) : "l"(a), "l"(b), "l"(c));
    return d;
}
__device__ __forceinline__ unsigned long long pack2(float v) {
    unsigned long long d;
    asm("mov.b64 %0, {%1, %1};" : "=l"(d) : "f"(v));
    return d;
}
__device__ __forceinline__ void unpack2(float& lo, float& hi, unsigned long long v) {
    asm("mov.b64 {%0, %1}, %2;" : "=f"(lo), "=f"(hi) : "l"(v));
}

__global__ __launch_bounds__(NTHREADS, 2)
void dwxcorr_kernel(const float* __restrict__ x,
                    const float* __restrict__ tm,
                    float* __restrict__ out)
{
    __shared__ float s_in[SROWS * SP];   // zero-padded input tile
    __shared__ float s_t[TAPS][NT];      // templates transposed: nt contiguous

    const int c   = blockIdx.x >> 1;            // fused (b, ch) channel
    const int y0  = (blockIdx.x & 1) * RPB;     // top output row of this half
    const int tid = threadIdx.x;

    const float* xc = x + (size_t)c * PLANE;

    // Fill padded input tile (zeros outside the plane), single pass.
    for (int i = tid; i < SROWS * SP; i += NTHREADS) {
        int r  = i / SP;
        int cc = i - r * SP;
        int gy = y0 + r - PAD;
        int gx = cc - PAD;
        float v = 0.0f;
        if (gy >= 0 && gy < HI && gx >= 0 && gx < WI)
            v = xc[gy * WI + gx];
        s_in[i] = v;
    }
    // Templates for this channel, transposed to [tap][nt] so adjacent nt pairs
    // are one 64-bit broadcast LDS in the mainloop.
    for (int i = tid; i < TAPS * NT; i += NTHREADS) {
        int nt  = i / TAPS;
        int tap = i - nt * TAPS;
        s_t[tap][nt] = tm[((size_t)nt * BSNC + c) * TAPS + tap];
    }
    __syncthreads();

    const int tx = tid & 7;   // 8 x-groups of 8 pixels
    const int ty = tid >> 3;  // 32 rows

    // acc[n2][px]: f32x2 pair over (nt=2*n2, nt=2*n2+1) for pixel px
    unsigned long long acc[4][8];
    #pragma unroll
    for (int a = 0; a < 4; a++)
        #pragma unroll
        for (int p = 0; p < 8; p++)
            acc[a][p] = 0ull;

    #pragma unroll 1
    for (int ky = 0; ky < KH; ky++) {
        const float* rp = &s_in[(ty + ky) * SP + tx * 8];
        float4 v0 = *(const float4*)(rp);
        float4 v1 = *(const float4*)(rp + 4);
        float4 v2 = *(const float4*)(rp + 8);
        float2 v3 = *(const float2*)(rp + 12);
        unsigned long long p[14];
        p[0]  = pack2(v0.x); p[1]  = pack2(v0.y); p[2]  = pack2(v0.z); p[3]  = pack2(v0.w);
        p[4]  = pack2(v1.x); p[5]  = pack2(v1.y); p[6]  = pack2(v1.z); p[7]  = pack2(v1.w);
        p[8]  = pack2(v2.x); p[9]  = pack2(v2.y); p[10] = pack2(v2.z); p[11] = pack2(v2.w);
        p[12] = pack2(v3.x); p[13] = pack2(v3.y);

        const unsigned long long* trow =
            (const unsigned long long*)&s_t[ky * KW][0];
        #pragma unroll
        for (int kx = 0; kx < KW; kx++) {
            unsigned long long t0 = trow[kx * 4 + 0];
            unsigned long long t1 = trow[kx * 4 + 1];
            unsigned long long t2 = trow[kx * 4 + 2];
            unsigned long long t3 = trow[kx * 4 + 3];
            #pragma unroll
            for (int px = 0; px < 8; px++) {
                acc[0][px] = ffma2(t0, p[px + kx], acc[0][px]);
                acc[1][px] = ffma2(t1, p[px + kx], acc[1][px]);
                acc[2][px] = ffma2(t2, p[px + kx], acc[2][px]);
                acc[3][px] = ffma2(t3, p[px + kx], acc[3][px]);
            }
        }
    }

    // Epilogue: unpack nt pairs, vectorized stores (2x STG.128 per nt).
    const size_t planeN = (size_t)BSNC * PLANE;  // stride between nt slabs
    float* ob = out + (size_t)c * PLANE + (size_t)(y0 + ty) * WI + tx * 8;
    #pragma unroll
    for (int n2 = 0; n2 < 4; n2++) {
        float lo[8], hi[8];
        #pragma unroll
        for (int px = 0; px < 8; px++) unpack2(lo[px], hi[px], acc[n2][px]);
        float* olo = ob + (size_t)(2 * n2)     * planeN;
        float* ohi = ob + (size_t)(2 * n2 + 1) * planeN;
        ((float4*)olo)[0] = make_float4(lo[0], lo[1], lo[2], lo[3]);
        ((float4*)olo)[1] = make_float4(lo[4], lo[5], lo[6], lo[7]);
        ((float4*)ohi)[0] = make_float4(hi[0], hi[1], hi[2], hi[3]);
        ((float4*)ohi)[1] = make_float4(hi[4], hi[5], hi[6], hi[7]);
    }
}

extern "C" void kernel_launch(void* const* d_in, const int* in_sizes, int n_in,
                              void* d_out, int out_size)
{
    const float* x  = (const float*)d_in[0];
    const float* tm = (const float*)d_in[1];
    float* out      = (float*)d_out;
    dwxcorr_kernel<<<BSNC * 2, NTHREADS>>>(x, tm, out);
}

// round 2
// speedup vs baseline: 1.2054x; 1.2054x over previous
#include <cuda_runtime.h>
#include <cuda_bf16.h>

// BatchDepthwiseCrossCorrelation:
//   x:         [8, 256, 64, 64]  f32
//   templates: [8, 8, 256, 7, 7] f32
//   out:       [8, 8, 256, 64, 64] f32
// out[nt,b,ch,y,x] = sum_{ky,kx} x[b,ch,y+ky-3,x+kx-3] * t[nt,b,ch,ky,kx]

#define BSNC   2048
#define HI     64
#define WI     64
#define PLANE  (HI*WI)
#define KH     7
#define KW     7
#define TAPS   49
#define PAD    3
#define NT     8
#define RPB    16              // output rows per block (4 blocks per channel)
#define SROWS  (RPB + KH - 1)  // 22
#define SP     72              // smem row pitch in words
#define NTHREADS 256

__device__ __forceinline__ unsigned long long ffma2(unsigned long long a,
                                                    unsigned long long b,
                                                    unsigned long long c) {
    unsigned long long d;
    asm("fma.rn.f32x2 %0, %1, %2, %3;" : "=l"(d) : "l"(a), "l"(b), "l"(c));
    return d;
}
__device__ __forceinline__ unsigned long long pack2(float v) {
    unsigned long long d;
    asm("mov.b64 %0, {%1, %1};" : "=l"(d) : "f"(v));
    return d;
}
__device__ __forceinline__ void unpack2(float& lo, float& hi, unsigned long long v) {
    asm("mov.b64 {%0, %1}, %2;" : "=f"(lo), "=f"(hi) : "l"(v));
}

__global__ __launch_bounds__(NTHREADS, 3)
void dwxcorr_kernel(const float* __restrict__ x,
                    const float* __restrict__ tm,
                    float* __restrict__ out)
{
    __shared__ float s_in[SROWS * SP];   // zero-padded input tile
    __shared__ float s_t[TAPS][NT];      // templates transposed: nt contiguous

    const int c   = blockIdx.x >> 2;            // fused (b, ch) channel
    const int y0  = (blockIdx.x & 3) * RPB;     // top output row of this quarter
    const int tid = threadIdx.x;

    const float* xc = x + (size_t)c * PLANE;

    // Fill padded input tile (zeros outside the plane).
    for (int i = tid; i < SROWS * SP; i += NTHREADS) {
        int r  = i / SP;
        int cc = i - r * SP;
        int gy = y0 + r - PAD;
        int gx = cc - PAD;
        float v = 0.0f;
        if (gy >= 0 && gy < HI && gx >= 0 && gx < WI)
            v = xc[gy * WI + gx];
        s_in[i] = v;
    }
    // Templates transposed to [tap][nt]: adjacent nt pairs = one 64-bit broadcast LDS.
    for (int i = tid; i < TAPS * NT; i += NTHREADS) {
        int nt  = i / TAPS;
        int tap = i - nt * TAPS;
        s_t[tap][nt] = tm[((size_t)nt * BSNC + c) * TAPS + tap];
    }
    __syncthreads();

    const int tx = tid & 15;  // 16 x-groups of 4 pixels
    const int ty = tid >> 4;  // 16 rows

    // acc[n2][px]: f32x2 pair over (nt=2*n2, nt=2*n2+1) for pixel px (4 pixels)
    unsigned long long acc[4][4];
    #pragma unroll
    for (int a = 0; a < 4; a++)
        #pragma unroll
        for (int p = 0; p < 4; p++)
            acc[a][p] = 0ull;

    #pragma unroll 1
    for (int ky = 0; ky < KH; ky++) {
        const float* rp = &s_in[(ty + ky) * SP + tx * 4];
        float4 v0 = *(const float4*)(rp);
        float4 v1 = *(const float4*)(rp + 4);
        float2 v2 = *(const float2*)(rp + 8);
        unsigned long long p[10];
        p[0] = pack2(v0.x); p[1] = pack2(v0.y); p[2] = pack2(v0.z); p[3] = pack2(v0.w);
        p[4] = pack2(v1.x); p[5] = pack2(v1.y); p[6] = pack2(v1.z); p[7] = pack2(v1.w);
        p[8] = pack2(v2.x); p[9] = pack2(v2.y);

        const unsigned long long* trow =
            (const unsigned long long*)&s_t[ky * KW][0];
        #pragma unroll
        for (int kx = 0; kx < KW; kx++) {
            unsigned long long t0 = trow[kx * 4 + 0];
            unsigned long long t1 = trow[kx * 4 + 1];
            unsigned long long t2 = trow[kx * 4 + 2];
            unsigned long long t3 = trow[kx * 4 + 3];
            #pragma unroll
            for (int px = 0; px < 4; px++) {
                acc[0][px] = ffma2(t0, p[px + kx], acc[0][px]);
                acc[1][px] = ffma2(t1, p[px + kx], acc[1][px]);
                acc[2][px] = ffma2(t2, p[px + kx], acc[2][px]);
                acc[3][px] = ffma2(t3, p[px + kx], acc[3][px]);
            }
        }
    }

    // Epilogue: unpack nt pairs, one STG.128 per nt slab.
    const size_t planeN = (size_t)BSNC * PLANE;  // stride between nt slabs
    float* ob = out + (size_t)c * PLANE + (size_t)(y0 + ty) * WI + tx * 4;
    #pragma unroll
    for (int n2 = 0; n2 < 4; n2++) {
        float lo[4], hi[4];
        #pragma unroll
        for (int px = 0; px < 4; px++) unpack2(lo[px], hi[px], acc[n2][px]);
        float* olo = ob + (size_t)(2 * n2)     * planeN;
        float* ohi = ob + (size_t)(2 * n2 + 1) * planeN;
        *(float4*)olo = make_float4(lo[0], lo[1], lo[2], lo[3]);
        *(float4*)ohi = make_float4(hi[0], hi[1], hi[2], hi[3]);
    }
}

extern "C" void kernel_launch(void* const* d_in, const int* in_sizes, int n_in,
                              void* d_out, int out_size)
{
    const float* x  = (const float*)d_in[0];
    const float* tm = (const float*)d_in[1];
    float* out      = (float*)d_out;
    dwxcorr_kernel<<<BSNC * 4, NTHREADS>>>(x, tm, out);
}

// round 3
// speedup vs baseline: 1.3120x; 1.0884x over previous
#include <cuda_runtime.h>
#include <cuda_bf16.h>

// BatchDepthwiseCrossCorrelation:
//   x:         [8, 256, 64, 64]  f32
//   templates: [8, 8, 256, 7, 7] f32
//   out:       [8, 8, 256, 64, 64] f32
// out[nt,b,ch,y,x] = sum_{ky,kx} x[b,ch,y+ky-3,x+kx-3] * t[nt,b,ch,ky,kx]

#define BSNC   2048
#define HI     64
#define WI     64
#define PLANE  (HI*WI)
#define KH     7
#define KW     7
#define TAPS   49
#define PAD    3
#define NT     8
#define RPB    16              // output rows per block (4 blocks per channel)
#define SROWS  (RPB + KH - 1)  // 22
#define SP     72              // smem row pitch in words
#define NTHREADS 256

__device__ __forceinline__ unsigned long long ffma2(unsigned long long a,
                                                    unsigned long long b,
                                                    unsigned long long c) {
    unsigned long long d;
    asm("fma.rn.f32x2 %0, %1, %2, %3;" : "=l"(d) : "l"(a), "l"(b), "l"(c));
    return d;
}
__device__ __forceinline__ unsigned long long pack2(float v) {
    unsigned long long d;
    asm("mov.b64 %0, {%1, %1};" : "=l"(d) : "f"(v));
    return d;
}
__device__ __forceinline__ void unpack2(float& lo, float& hi, unsigned long long v) {
    asm("mov.b64 {%0, %1}, %2;" : "=f"(lo), "=f"(hi) : "l"(v));
}

__global__ __launch_bounds__(NTHREADS, 4)
void dwxcorr_kernel(const float* __restrict__ x,
                    const float* __restrict__ tm,
                    float* __restrict__ out)
{
    __shared__ float s_in[SROWS * SP];                  // zero-padded input tile
    __shared__ __align__(16) float s_t[TAPS][NT];       // templates: [tap][nt]

    const int c   = blockIdx.x >> 2;            // fused (b, ch) channel
    const int y0  = (blockIdx.x & 3) * RPB;     // top output row of this quarter
    const int tid = threadIdx.x;

    const float* xc = x + (size_t)c * PLANE;

    // Fill padded input tile (zeros outside the plane).
    for (int i = tid; i < SROWS * SP; i += NTHREADS) {
        int r  = i / SP;
        int cc = i - r * SP;
        int gy = y0 + r - PAD;
        int gx = cc - PAD;
        float v = 0.0f;
        if (gy >= 0 && gy < HI && gx >= 0 && gx < WI)
            v = xc[gy * WI + gx];
        s_in[i] = v;
    }
    // Templates transposed to [tap][nt]: adjacent nt quads load as LDS.128.
    for (int i = tid; i < TAPS * NT; i += NTHREADS) {
        int nt  = i / TAPS;
        int tap = i - nt * TAPS;
        s_t[tap][nt] = tm[((size_t)nt * BSNC + c) * TAPS + tap];
    }
    __syncthreads();

    const int tx = tid & 15;  // 16 x-groups of 4 pixels
    const int ty = tid >> 4;  // 16 rows

    // acc[n2][px]: f32x2 pair over (nt=2*n2, nt=2*n2+1) for pixel px (4 pixels)
    unsigned long long acc[4][4];
    #pragma unroll
    for (int a = 0; a < 4; a++)
        #pragma unroll
        for (int p = 0; p < 4; p++)
            acc[a][p] = 0ull;

    #pragma unroll 1
    for (int ky = 0; ky < KH; ky++) {
        const float* rp = &s_in[(ty + ky) * SP + tx * 4];
        float4 v0 = *(const float4*)(rp);
        float4 v1 = *(const float4*)(rp + 4);
        float2 v2 = *(const float2*)(rp + 8);
        unsigned long long p[10];
        p[0] = pack2(v0.x); p[1] = pack2(v0.y); p[2] = pack2(v0.z); p[3] = pack2(v0.w);
        p[4] = pack2(v1.x); p[5] = pack2(v1.y); p[6] = pack2(v1.z); p[7] = pack2(v1.w);
        p[8] = pack2(v2.x); p[9] = pack2(v2.y);

        const ulonglong2* trow = (const ulonglong2*)&s_t[ky * KW][0];
        #pragma unroll
        for (int kx = 0; kx < KW; kx++) {
            ulonglong2 ta = trow[kx * 2 + 0];   // {t0, t1} pairs (nt 0-3)
            ulonglong2 tb = trow[kx * 2 + 1];   // {t2, t3} pairs (nt 4-7)
            #pragma unroll
            for (int px = 0; px < 4; px++) {
                acc[0][px] = ffma2(ta.x, p[px + kx], acc[0][px]);
                acc[1][px] = ffma2(ta.y, p[px + kx], acc[1][px]);
                acc[2][px] = ffma2(tb.x, p[px + kx], acc[2][px]);
                acc[3][px] = ffma2(tb.y, p[px + kx], acc[3][px]);
            }
        }
    }

    // Epilogue: unpack nt pairs, one STG.128 per nt slab.
    const size_t planeN = (size_t)BSNC * PLANE;  // stride between nt slabs
    float* ob = out + (size_t)c * PLANE + (size_t)(y0 + ty) * WI + tx * 4;
    #pragma unroll
    for (int n2 = 0; n2 < 4; n2++) {
        float lo[4], hi[4];
        #pragma unroll
        for (int px = 0; px < 4; px++) unpack2(lo[px], hi[px], acc[n2][px]);
        float* olo = ob + (size_t)(2 * n2)     * planeN;
        float* ohi = ob + (size_t)(2 * n2 + 1) * planeN;
        *(float4*)olo = make_float4(lo[0], lo[1], lo[2], lo[3]);
        *(float4*)ohi = make_float4(hi[0], hi[1], hi[2], hi[3]);
    }
}

extern "C" void kernel_launch(void* const* d_in, const int* in_sizes, int n_in,
                              void* d_out, int out_size)
{
    const float* x  = (const float*)d_in[0];
    const float* tm = (const float*)d_in[1];
    float* out      = (float*)d_out;
    dwxcorr_kernel<<<BSNC * 4, NTHREADS>>>(x, tm, out);
}

// round 4
// speedup vs baseline: 1.5110x; 1.1517x over previous
#include <cuda_runtime.h>
#include <cuda_bf16.h>

// BatchDepthwiseCrossCorrelation:
//   x:         [8, 256, 64, 64]  f32
//   templates: [8, 8, 256, 7, 7] f32
//   out:       [8, 8, 256, 64, 64] f32
// out[nt,b,ch,y,x] = sum_{ky,kx} x[b,ch,y+ky-3,x+kx-3] * t[nt,b,ch,ky,kx]

#define BSNC   2048
#define HI     64
#define WI     64
#define PLANE  (HI*WI)
#define KH     7
#define KW     7
#define TAPS   49
#define PAD    3
#define NT     8
#define RPB    16              // output rows per quarter
#define NQ     4               // quarters per channel
#define SROWS  (HI + KH - 1)   // 70 padded rows (whole plane)
#define SP     72              // smem row pitch in words (16B-aligned rows)
#define NTHREADS 256

__device__ __forceinline__ unsigned long long ffma2(unsigned long long a,
                                                    unsigned long long b,
                                                    unsigned long long c) {
    unsigned long long d;
    asm("fma.rn.f32x2 %0, %1, %2, %3;" : "=l"(d) : "l"(a), "l"(b), "l"(c));
    return d;
}
__device__ __forceinline__ unsigned long long pack2(float v) {
    unsigned long long d;
    asm("mov.b64 %0, {%1, %1};" : "=l"(d) : "f"(v));
    return d;
}
__device__ __forceinline__ void unpack2(float& lo, float& hi, unsigned long long v) {
    asm("mov.b64 {%0, %1}, %2;" : "=f"(lo), "=f"(hi) : "l"(v));
}

__global__ __launch_bounds__(NTHREADS, 4)
void dwxcorr_kernel(const float* __restrict__ x,
                    const float* __restrict__ tm,
                    float* __restrict__ out)
{
    __shared__ float s_in[SROWS * SP];                 // whole zero-padded plane
    __shared__ __align__(16) float s_t[TAPS][NT];      // templates: [tap][nt]

    const int c   = blockIdx.x;        // fused (b, ch) channel
    const int tid = threadIdx.x;
    const float* xc = x + (size_t)c * PLANE;

    // Phase 1: zero-fill the padded tile (branch-free).
    for (int i = tid; i < SROWS * SP; i += NTHREADS)
        s_in[i] = 0.0f;
    // Templates transposed to [tap][nt]: adjacent nt quads load as LDS.128.
    for (int i = tid; i < TAPS * NT; i += NTHREADS) {
        int nt  = i / TAPS;
        int tap = i - nt * TAPS;
        s_t[tap][nt] = tm[((size_t)nt * BSNC + c) * TAPS + tap];
    }
    __syncthreads();

    // Phase 2: coalesced interior copy, no predication, no division.
    for (int i = tid; i < PLANE; i += NTHREADS) {
        int r  = i >> 6;
        int cc = i & 63;
        s_in[(r + PAD) * SP + cc + PAD] = xc[i];
    }
    __syncthreads();

    const int tx = tid & 15;  // 16 x-groups of 4 pixels
    const int ty = tid >> 4;  // 16 rows within a quarter

    const size_t planeN = (size_t)BSNC * PLANE;  // stride between nt slabs

    #pragma unroll 1
    for (int yq = 0; yq < NQ; yq++) {
        const int row0 = yq * RPB + ty;   // output row; padded input rows row0..row0+6

        // acc[n2][px]: f32x2 pair over (nt=2*n2, nt=2*n2+1) for pixel px
        unsigned long long acc[4][4];
        #pragma unroll
        for (int a = 0; a < 4; a++)
            #pragma unroll
            for (int p = 0; p < 4; p++)
                acc[a][p] = 0ull;

        #pragma unroll 1
        for (int ky = 0; ky < KH; ky++) {
            const float* rp = &s_in[(row0 + ky) * SP + tx * 4];
            float4 v0 = *(const float4*)(rp);
            float4 v1 = *(const float4*)(rp + 4);
            float2 v2 = *(const float2*)(rp + 8);
            unsigned long long p[10];
            p[0] = pack2(v0.x); p[1] = pack2(v0.y); p[2] = pack2(v0.z); p[3] = pack2(v0.w);
            p[4] = pack2(v1.x); p[5] = pack2(v1.y); p[6] = pack2(v1.z); p[7] = pack2(v1.w);
            p[8] = pack2(v2.x); p[9] = pack2(v2.y);

            const ulonglong2* trow = (const ulonglong2*)&s_t[ky * KW][0];
            #pragma unroll
            for (int kx = 0; kx < KW; kx++) {
                ulonglong2 ta = trow[kx * 2 + 0];   // nt pairs {0-1, 2-3}
                ulonglong2 tb = trow[kx * 2 + 1];   // nt pairs {4-5, 6-7}
                #pragma unroll
                for (int px = 0; px < 4; px++) {
                    acc[0][px] = ffma2(ta.x, p[px + kx], acc[0][px]);
                    acc[1][px] = ffma2(ta.y, p[px + kx], acc[1][px]);
                    acc[2][px] = ffma2(tb.x, p[px + kx], acc[2][px]);
                    acc[3][px] = ffma2(tb.y, p[px + kx], acc[3][px]);
                }
            }
        }

        // Epilogue: unpack nt pairs, one STG.128 per nt slab.
        float* ob = out + (size_t)c * PLANE + (size_t)row0 * WI + tx * 4;
        #pragma unroll
        for (int n2 = 0; n2 < 4; n2++) {
            float lo[4], hi[4];
            #pragma unroll
            for (int px = 0; px < 4; px++) unpack2(lo[px], hi[px], acc[n2][px]);
            float* olo = ob + (size_t)(2 * n2)     * planeN;
            float* ohi = ob + (size_t)(2 * n2 + 1) * planeN;
            *(float4*)olo = make_float4(lo[0], lo[1], lo[2], lo[3]);
            *(float4*)ohi = make_float4(hi[0], hi[1], hi[2], hi[3]);
        }
    }
}

extern "C" void kernel_launch(void* const* d_in, const int* in_sizes, int n_in,
                              void* d_out, int out_size)
{
    const float* x  = (const float*)d_in[0];
    const float* tm = (const float*)d_in[1];
    float* out      = (float*)d_out;
    dwxcorr_kernel<<<BSNC, NTHREADS>>>(x, tm, out);
}

// round 5
// speedup vs baseline: 1.5113x; 1.0002x over previous
#include <cuda_runtime.h>
#include <cuda_bf16.h>

// BatchDepthwiseCrossCorrelation:
//   x:         [8, 256, 64, 64]  f32
//   templates: [8, 8, 256, 7, 7] f32
//   out:       [8, 8, 256, 64, 64] f32
// out[nt,b,ch,y,x] = sum_{ky,kx} x[b,ch,y+ky-3,x+kx-3] * t[nt,b,ch,ky,kx]

#define BSNC   2048
#define HI     64
#define WI     64
#define PLANE  (HI*WI)
#define KH     7
#define KW     7
#define TAPS   49
#define PAD    3
#define NT     8
#define HROWS  32              // output rows per CTA (half plane)
#define RPB    16              // output rows per quarter pass
#define NQ     2               // passes per CTA
#define SROWS  (HROWS + KH - 1) // 38 padded rows
#define SP     72              // smem row pitch in words (16B-aligned rows)
#define NTHREADS 256

__device__ __forceinline__ unsigned long long ffma2(unsigned long long a,
                                                    unsigned long long b,
                                                    unsigned long long c) {
    unsigned long long d;
    asm("fma.rn.f32x2 %0, %1, %2, %3;" : "=l"(d) : "l"(a), "l"(b), "l"(c));
    return d;
}
__device__ __forceinline__ unsigned long long pack2(float v) {
    unsigned long long d;
    asm("mov.b64 %0, {%1, %1};" : "=l"(d) : "f"(v));
    return d;
}
__device__ __forceinline__ void unpack2(float& lo, float& hi, unsigned long long v) {
    asm("mov.b64 {%0, %1}, %2;" : "=f"(lo), "=f"(hi) : "l"(v));
}

__global__ __launch_bounds__(NTHREADS, 4)
void dwxcorr_kernel(const float* __restrict__ x,
                    const float* __restrict__ tm,
                    float* __restrict__ out)
{
    __shared__ float s_in[SROWS * SP];                 // zero-padded half-plane
    __shared__ __align__(16) float s_t[TAPS][NT];      // templates: [tap][nt]

    const int c   = blockIdx.x >> 1;            // fused (b, ch) channel
    const int y0  = (blockIdx.x & 1) * HROWS;   // top output row of this half
    const int tid = threadIdx.x;
    const float* xc = x + (size_t)c * PLANE;

    // Phase 1: zero-fill the padded tile (branch-free) + template transpose.
    for (int i = tid; i < SROWS * SP; i += NTHREADS)
        s_in[i] = 0.0f;
    for (int i = tid; i < TAPS * NT; i += NTHREADS) {
        int nt  = i / TAPS;
        int tap = i - nt * TAPS;
        s_t[tap][nt] = tm[((size_t)nt * BSNC + c) * TAPS + tap];
    }
    __syncthreads();

    // Phase 2: coalesced interior copy (rows y0-3 .. y0+34, clamped to plane).
    {
        int gy_lo = y0 - PAD;                    // first global row of tile
        int r_begin = (gy_lo < 0) ? PAD : 0;     // skip rows above the plane
        int nrows = SROWS;
        if (gy_lo + SROWS > HI) nrows = HI - gy_lo;   // clip rows below plane
        // copy rows r in [r_begin, nrows): global row gy_lo + r
        int total = (nrows - r_begin) * WI;
        const float* src = xc + (size_t)(gy_lo + r_begin) * WI;
        for (int i = tid; i < total; i += NTHREADS) {
            int r  = i >> 6;
            int cc = i & 63;
            s_in[(r_begin + r) * SP + cc + PAD] = src[i];
        }
    }
    __syncthreads();

    const int tx = tid & 15;  // 16 x-groups of 4 pixels
    const int ty = tid >> 4;  // 16 rows within a pass

    const size_t planeN = (size_t)BSNC * PLANE;  // stride between nt slabs

    #pragma unroll 1
    for (int yq = 0; yq < NQ; yq++) {
        const int rloc = yq * RPB + ty;          // row within this CTA's half

        unsigned long long acc[4][4];
        #pragma unroll
        for (int a = 0; a < 4; a++)
            #pragma unroll
            for (int p = 0; p < 4; p++)
                acc[a][p] = 0ull;

        #pragma unroll 1
        for (int ky = 0; ky < KH; ky++) {
            const float* rp = &s_in[(rloc + ky) * SP + tx * 4];
            float4 v0 = *(const float4*)(rp);
            float4 v1 = *(const float4*)(rp + 4);
            float2 v2 = *(const float2*)(rp + 8);
            unsigned long long p[10];
            p[0] = pack2(v0.x); p[1] = pack2(v0.y); p[2] = pack2(v0.z); p[3] = pack2(v0.w);
            p[4] = pack2(v1.x); p[5] = pack2(v1.y); p[6] = pack2(v1.z); p[7] = pack2(v1.w);
            p[8] = pack2(v2.x); p[9] = pack2(v2.y);

            const ulonglong2* trow = (const ulonglong2*)&s_t[ky * KW][0];
            #pragma unroll
            for (int kx = 0; kx < KW; kx++) {
                ulonglong2 ta = trow[kx * 2 + 0];   // nt pairs {0-1, 2-3}
                ulonglong2 tb = trow[kx * 2 + 1];   // nt pairs {4-5, 6-7}
                #pragma unroll
                for (int px = 0; px < 4; px++) {
                    acc[0][px] = ffma2(ta.x, p[px + kx], acc[0][px]);
                    acc[1][px] = ffma2(ta.y, p[px + kx], acc[1][px]);
                    acc[2][px] = ffma2(tb.x, p[px + kx], acc[2][px]);
                    acc[3][px] = ffma2(tb.y, p[px + kx], acc[3][px]);
                }
            }
        }

        // Epilogue: unpack nt pairs, one STG.128 per nt slab.
        float* ob = out + (size_t)c * PLANE + (size_t)(y0 + rloc) * WI + tx * 4;
        #pragma unroll
        for (int n2 = 0; n2 < 4; n2++) {
            float lo[4], hi[4];
            #pragma unroll
            for (int px = 0; px < 4; px++) unpack2(lo[px], hi[px], acc[n2][px]);
            float* olo = ob + (size_t)(2 * n2)     * planeN;
            float* ohi = ob + (size_t)(2 * n2 + 1) * planeN;
            *(float4*)olo = make_float4(lo[0], lo[1], lo[2], lo[3]);
            *(float4*)ohi = make_float4(hi[0], hi[1], hi[2], hi[3]);
        }
    }
}

extern "C" void kernel_launch(void* const* d_in, const int* in_sizes, int n_in,
                              void* d_out, int out_size)
{
    const float* x  = (const float*)d_in[0];
    const float* tm = (const float*)d_in[1];
    float* out      = (float*)d_out;
    dwxcorr_kernel<<<BSNC * 2, NTHREADS>>>(x, tm, out);
}

// round 7
// speedup vs baseline: 1.8345x; 1.2139x over previous
#include <cuda_runtime.h>
#include <cuda_bf16.h>
#include <cstdint>

// BatchDepthwiseCrossCorrelation via warp-level HMMA (mma.sync bf16, 3-pass hi/lo split).
//   x:         [8, 256, 64, 64]  f32
//   templates: [8, 8, 256, 7, 7] f32
//   out:       [8, 8, 256, 64, 64] f32
// Per channel c: out[p, nt] = sum_tap patch[p, tap] * t[nt, tap]
// GEMM: M = pixels (16/warp-tile), N = 8 (nt, exactly n8), K = 64 (taps, ky*8+kx; kx=7 & ky=7 zero in B)

#define BSNC   2048
#define HI     64
#define WI     64
#define PLANE  (HI*WI)
#define PAD    3
#define NT     8
#define QROWS  16                 // output rows per CTA (quarter plane)
#define SROWS  23                 // padded input rows staged (ty+ky max = 15+7 = 22)
#define SPW    72                 // plane row pitch in u32 words
#define KDIM   64
#define NTHREADS 128

__device__ __forceinline__ uint32_t split_pack(float v) {
    __nv_bfloat16 h = __float2bfloat16(v);
    float hf = __bfloat162float(h);
    __nv_bfloat16 l = __float2bfloat16(v - hf);
    return ((uint32_t)__bfloat16_as_ushort(h) << 16) | (uint32_t)__bfloat16_as_ushort(l);
}

__device__ __forceinline__ void mma_bf16(float& d0, float& d1, float& d2, float& d3,
                                         uint32_t a0, uint32_t a1, uint32_t a2, uint32_t a3,
                                         uint32_t b0, uint32_t b1) {
    asm volatile(
        "mma.sync.aligned.m16n8k16.row.col.f32.bf16.bf16.f32 "
        "{%0,%1,%2,%3}, {%4,%5,%6,%7}, {%8,%9}, {%0,%1,%2,%3};"
        : "+f"(d0), "+f"(d1), "+f"(d2), "+f"(d3)
        : "r"(a0), "r"(a1), "r"(a2), "r"(a3), "r"(b0), "r"(b1));
}

__global__ __launch_bounds__(NTHREADS, 8)
void dwxcorr_hmma_kernel(const float* __restrict__ x,
                         const float* __restrict__ tm,
                         float* __restrict__ out)
{
    __shared__ uint32_t s_plane[SROWS * SPW];          // packed {bf16 hi | bf16 lo}
    __shared__ __align__(16) uint32_t s_tmpl[NT][KDIM]; // packed templates, tap = ky*8+kx

    const int c   = blockIdx.x >> 2;            // fused (b, ch) channel
    const int y0  = (blockIdx.x & 3) * QROWS;   // top output row of this quarter
    const int tid = threadIdx.x;
    const int wid = tid >> 5;
    const int lane = tid & 31;
    const int q = lane & 3;                     // quad-pair index
    const int r = lane >> 2;                    // row-in-group index

    // ---- Prologue: zero-fill plane + template buffers ----
    for (int i = tid; i < SROWS * SPW; i += NTHREADS) s_plane[i] = 0u;
    for (int i = tid; i < NT * KDIM; i += NTHREADS) ((uint32_t*)s_tmpl)[i] = 0u;
    __syncthreads();

    // Interior copy: padded rows a (plane row gy = y0 + a - 3), real taps use a <= 21.
    {
        const int a0 = (y0 == 0) ? PAD : 0;
        int a1 = 66 - y0; if (a1 > 21) a1 = 21;
        const int nrows = a1 - a0 + 1;
        const float* src = x + (size_t)c * PLANE + (size_t)(y0 + a0 - PAD) * WI;
        for (int i = tid; i < nrows * WI; i += NTHREADS) {
            int rr = i >> 6;
            int cc = i & 63;
            s_plane[(a0 + rr) * SPW + cc + PAD] = split_pack(src[i]);
        }
    }
    // Templates: scatter taps into [nt][ky*8+kx] (kx=7, ky=7 stay zero).
    for (int i = tid; i < NT * 49; i += NTHREADS) {
        int nt = i / 49, tap = i - nt * 49;
        int ky = tap / 7, kx = tap - ky * 7;
        s_tmpl[nt][ky * 8 + kx] = split_pack(tm[((size_t)nt * BSNC + c) * 49 + tap]);
    }
    __syncthreads();

    // ---- B fragments (templates) into registers: loop-invariant per channel ----
    // b0 = {B[16ch+2q][n], B[16ch+2q+1][n]}, b1 = {+8}, n = r.
    uint32_t bh[8], bl[8];
    {
        const uint32_t* tb = &s_tmpl[r][2 * q];
        #pragma unroll
        for (int ch = 0; ch < 4; ch++) {
            uint2 w = *(const uint2*)(tb + ch * 16);
            bh[2 * ch]     = __byte_perm(w.x, w.y, 0x7632);
            bl[2 * ch]     = __byte_perm(w.x, w.y, 0x5410);
            uint2 v = *(const uint2*)(tb + ch * 16 + 8);
            bh[2 * ch + 1] = __byte_perm(v.x, v.y, 0x7632);
            bl[2 * ch + 1] = __byte_perm(v.x, v.y, 0x5410);
        }
    }

    const size_t planeN = (size_t)BSNC * PLANE;
    float* obase = out + (size_t)c * PLANE + (size_t)y0 * WI;

    // ---- Mainloop: 16 warp-tiles per warp, no barriers ----
    #pragma unroll 1
    for (int i = 0; i < 16; i++) {
        const int t  = wid * 16 + i;
        const int ty = t >> 2;            // output row within quarter (0..15)
        const int x0 = (t & 3) << 4;      // 16-pixel x group

        // A base for this thread: element (row r, col 2q) of the 16x64 im2col tile.
        const uint32_t* ap = &s_plane[ty * SPW + x0 + r + 2 * q];

        float d0 = 0.f, d1 = 0.f, d2 = 0.f, d3 = 0.f;

        #pragma unroll
        for (int ch = 0; ch < 4; ch++) {
            const uint32_t* p0 = ap + (2 * ch) * SPW;       // ky = 2ch
            const uint32_t* p1 = ap + (2 * ch + 1) * SPW;   // ky = 2ch+1
            uint32_t w00 = p0[0], w01 = p0[1];              // (r,   2q), (r,   2q+1)
            uint32_t w10 = p0[8], w11 = p0[9];              // (r+8, 2q), (r+8, 2q+1)
            uint32_t w20 = p1[0], w21 = p1[1];              // (r,   2q+8), ...
            uint32_t w30 = p1[8], w31 = p1[9];

            uint32_t ah0 = __byte_perm(w00, w01, 0x7632), al0 = __byte_perm(w00, w01, 0x5410);
            uint32_t ah1 = __byte_perm(w10, w11, 0x7632), al1 = __byte_perm(w10, w11, 0x5410);
            uint32_t ah2 = __byte_perm(w20, w21, 0x7632), al2 = __byte_perm(w20, w21, 0x5410);
            uint32_t ah3 = __byte_perm(w30, w31, 0x7632), al3 = __byte_perm(w30, w31, 0x5410);

            mma_bf16(d0, d1, d2, d3, ah0, ah1, ah2, ah3, bh[2 * ch], bh[2 * ch + 1]);
            mma_bf16(d0, d1, d2, d3, ah0, ah1, ah2, ah3, bl[2 * ch], bl[2 * ch + 1]);
            mma_bf16(d0, d1, d2, d3, al0, al1, al2, al3, bh[2 * ch], bh[2 * ch + 1]);
        }

        // D: c0 at (pixel r, nt 2q), c1 at (r, 2q+1), c2 at (r+8, 2q), c3 at (r+8, 2q+1)
        float* ob = obase + (size_t)ty * WI + x0 + r + (size_t)(2 * q) * planeN;
        ob[0]          = d0;
        ob[planeN]     = d1;
        ob[8]          = d2;
        ob[planeN + 8] = d3;
    }
}

extern "C" void kernel_launch(void* const* d_in, const int* in_sizes, int n_in,
                              void* d_out, int out_size)
{
    const float* x  = (const float*)d_in[0];
    const float* tm = (const float*)d_in[1];
    float* out      = (float*)d_out;
    dwxcorr_hmma_kernel<<<BSNC * 4, NTHREADS>>>(x, tm, out);
}